// round 6
// baseline (speedup 1.0000x reference)
#include <cuda_runtime.h>

// ---------------------------------------------------------------------------
// 2-layer LSTM (relu cell activation), B=128, T=512, F=64, U1=256, U2=128.
// Persistent flag-synced recurrence kernels, fp32 via packed fma.rn.f32x2.
// ---------------------------------------------------------------------------

#define T_STEPS 512
#define BATCH   128
#define FEAT    64
#define U1N     256
#define U2N     128

// Layer 1 tiling: 8 batch-tiles x 16 unit-tiles = 128 CTAs, 256 thr (16b x 16u)
#define L1_BT     16
#define L1_BTILES 8
#define L1_UT     16
#define L1_UTILES 16
#define L1_K      320   // 64 (x part) + 256 (h part)
#define L1_P      324   // padded sh_a row (floats), mult of 4

// Layer 2 tiling: 8 batch-tiles x 16 unit-tiles = 128 CTAs, 256 thr
// (16b x 8u x 2 k-halves, reduced in smem)
#define L2_BT     16
#define L2_BTILES 8
#define L2_UT     8
#define L2_UTILES 16
#define L2_K      384   // 256 (h1 input) + 128 (h2 recurrent)
#define L2_P      388

// Scratch (device globals: the sanctioned no-alloc workaround)
__device__ float g_h1[T_STEPS][U1N][BATCH];   // layer-1 hidden sequence
__device__ float g_h2[T_STEPS][U2N][BATCH];   // layer-2 hidden sequence
__device__ int   g_ctr1[T_STEPS * L1_BTILES];
__device__ int   g_ctr2[T_STEPS * L2_BTILES];

// ---------------------------------------------------------------------------
// f32x2 packed-math helpers (sm_103a)
// ---------------------------------------------------------------------------
__device__ __forceinline__ unsigned long long pack2(float x) {
    unsigned long long r;
    asm("mov.b64 %0, {%1, %1};" : "=l"(r) : "f"(x));
    return r;
}
__device__ __forceinline__ unsigned long long packpair(float lo, float hi) {
    unsigned long long r;
    asm("mov.b64 %0, {%1, %2};" : "=l"(r) : "f"(lo), "f"(hi));
    return r;
}
__device__ __forceinline__ void unpack2(unsigned long long v, float& lo, float& hi) {
    asm("mov.b64 {%0, %1}, %2;" : "=f"(lo), "=f"(hi) : "l"(v));
}
__device__ __forceinline__ unsigned long long ffma2(unsigned long long a,
                                                    unsigned long long b,
                                                    unsigned long long c) {
    unsigned long long d;
    asm("fma.rn.f32x2 %0, %1, %2, %3;" : "=l"(d) : "l"(a), "l"(b), "l"(c));
    return d;
}
__device__ __forceinline__ unsigned long long fadd2(unsigned long long a,
                                                    unsigned long long b) {
    unsigned long long d;
    asm("add.rn.f32x2 %0, %1, %2;" : "=l"(d) : "l"(a), "l"(b));
    return d;
}
__device__ __forceinline__ float sigmoidf_(float z) {
    return 1.0f / (1.0f + __expf(-z));
}
__device__ __forceinline__ int ld_acquire(const int* p) {
    int v;
    asm volatile("ld.acquire.gpu.u32 %0, [%1];" : "=r"(v) : "l"(p));
    return v;
}

// ---------------------------------------------------------------------------
// Counter reset (per launch, so graph replays are deterministic)
// ---------------------------------------------------------------------------
__global__ void reset_kernel() {
    int i = blockIdx.x * blockDim.x + threadIdx.x;
    if (i < T_STEPS * L1_BTILES) g_ctr1[i] = 0;
    if (i < T_STEPS * L2_BTILES) g_ctr2[i] = 0;
}

// ---------------------------------------------------------------------------
// Layer 1 persistent recurrence.
// CTA (ui, bi): units [ui*16, ui*16+16), batch [bi*16, bi*16+16).
// Thread (bl = tid&15, ul = tid>>4) owns one (b, u): 4 gate accumulators
// packed as two f32x2 values, cell state c in a register.
// Weights [320 k][16 u][4 gates] resident in smem for all 512 steps.
// ---------------------------------------------------------------------------
__global__ __launch_bounds__(256, 1)
void lstm_layer1(const float* __restrict__ x,  const float* __restrict__ W1,
                 const float* __restrict__ U1, const float* __restrict__ b1) {
    extern __shared__ float sm[];
    float* sh_w = sm;                      // [320][16][4] = 20480 floats
    float* sh_a = sm + L1_K * 64;          // [16][L1_P]   =  5184 floats

    const int tid = threadIdx.x;
    const int ui = blockIdx.x, bi = blockIdx.y;
    const int u0 = ui * L1_UT, b0 = bi * L1_BT;
    const int bl = tid & 15, ul = tid >> 4;

    // one-time weight load: rows 0..63 = W1, rows 64..319 = U1
    for (int i = tid; i < L1_K * 64; i += 256) {
        int k = i >> 6, r = i & 63;
        int uu = r >> 2, gi = r & 3;
        float w;
        if (k < FEAT) w = W1[k * 1024 + gi * 256 + u0 + uu];
        else          w = U1[(k - FEAT) * 1024 + gi * 256 + u0 + uu];
        sh_w[i] = w;
    }
    const unsigned long long bias01 =
        packpair(b1[0 * 256 + u0 + ul], b1[1 * 256 + u0 + ul]);
    const unsigned long long bias23 =
        packpair(b1[2 * 256 + u0 + ul], b1[3 * 256 + u0 + ul]);
    float c = 0.0f;
    __syncthreads();

    for (int t = 0; t < T_STEPS; ++t) {
        // stage x_t slice, transposed to sh_a[b][f]
        for (int i = tid; i < L1_BT * FEAT; i += 256) {
            int b = i >> 6, f = i & 63;
            sh_a[b * L1_P + f] = x[((b0 + b) * T_STEPS + t) * FEAT + f];
        }
        int kmax = FEAT;
        if (t > 0) {
            if (tid == 0) {
                const int* p = &g_ctr1[(t - 1) * L1_BTILES + bi];
                while (ld_acquire(p) < L1_UTILES) __nanosleep(32);
            }
            __syncthreads();
            for (int i = tid; i < L1_BT * U1N; i += 256) {
                int b = i & 15, u = i >> 4;
                sh_a[b * L1_P + FEAT + u] = g_h1[t - 1][u][b0 + b];
            }
            kmax = L1_K;
        }
        __syncthreads();

        unsigned long long acc01 = bias01, acc23 = bias23;
        const float* arow = sh_a + bl * L1_P;
        const ulonglong2* wb = reinterpret_cast<const ulonglong2*>(sh_w) + ul;
#pragma unroll 4
        for (int k = 0; k < kmax; k += 4) {
            float4 av = *reinterpret_cast<const float4*>(arow + k);
            unsigned long long a0 = pack2(av.x), a1 = pack2(av.y);
            unsigned long long a2 = pack2(av.z), a3 = pack2(av.w);
            ulonglong2 w0 = wb[(k + 0) * 16];
            ulonglong2 w1 = wb[(k + 1) * 16];
            ulonglong2 w2 = wb[(k + 2) * 16];
            ulonglong2 w3 = wb[(k + 3) * 16];
            acc01 = ffma2(a0, w0.x, acc01);  acc23 = ffma2(a0, w0.y, acc23);
            acc01 = ffma2(a1, w1.x, acc01);  acc23 = ffma2(a1, w1.y, acc23);
            acc01 = ffma2(a2, w2.x, acc01);  acc23 = ffma2(a2, w2.y, acc23);
            acc01 = ffma2(a3, w3.x, acc01);  acc23 = ffma2(a3, w3.y, acc23);
        }

        float zi, zf, zg, zo;
        unpack2(acc01, zi, zf);
        unpack2(acc23, zg, zo);
        float ig = sigmoidf_(zi), fg = sigmoidf_(zf);
        float gg = fmaxf(zg, 0.0f), og = sigmoidf_(zo);
        c = fg * c + ig * gg;
        float h = og * fmaxf(c, 0.0f);
        g_h1[t][u0 + ul][b0 + bl] = h;

        __syncthreads();
        if (tid == 0) {
            __threadfence();
            atomicAdd(&g_ctr1[t * L1_BTILES + bi], 1);
        }
    }
}

// ---------------------------------------------------------------------------
// Layer 2 persistent recurrence. Input x_t = h1_seq[t] (from layer 1).
// 256 threads: (bl, ul, kh) = (tid&15, (tid>>4)&7, tid>>7); two k-halves
// reduced through smem so we keep 8 warps/CTA (2 per SMSP) for FFMA2 rate.
// ---------------------------------------------------------------------------
__global__ __launch_bounds__(256, 1)
void lstm_layer2(const float* __restrict__ W2, const float* __restrict__ U2,
                 const float* __restrict__ b2, float* __restrict__ out) {
    extern __shared__ float sm[];
    float* sh_w = sm;                                 // [384][8][4] = 12288 floats
    float* sh_a = sm + L2_K * 32;                     // [16][L2_P]  =  6208 floats
    unsigned long long* sh_red =
        reinterpret_cast<unsigned long long*>(sh_a + L2_BT * L2_P);  // [128][2]

    const int tid = threadIdx.x;
    const int ui = blockIdx.x, bi = blockIdx.y;
    const int u0 = ui * L2_UT, b0 = bi * L2_BT;
    const int bl = tid & 15, ul = (tid >> 4) & 7, kh = tid >> 7;

    for (int i = tid; i < L2_K * 32; i += 256) {
        int k = i >> 5, r = i & 31;
        int uu = r >> 2, gi = r & 3;
        float w;
        if (k < U1N) w = W2[k * 512 + gi * 128 + u0 + uu];
        else         w = U2[(k - U1N) * 512 + gi * 128 + u0 + uu];
        sh_w[i] = w;
    }
    unsigned long long bias01 = 0ULL, bias23 = 0ULL;
    if (kh == 0) {
        bias01 = packpair(b2[0 * 128 + u0 + ul], b2[1 * 128 + u0 + ul]);
        bias23 = packpair(b2[2 * 128 + u0 + ul], b2[3 * 128 + u0 + ul]);
    }
    float c = 0.0f;
    __syncthreads();

    for (int t = 0; t < T_STEPS; ++t) {
        // stage h1_t slice (k = 0..255)
        for (int i = tid; i < L2_BT * U1N; i += 256) {
            int b = i & 15, u = i >> 4;
            sh_a[b * L2_P + u] = g_h1[t][u][b0 + b];
        }
        int kmax = U1N;
        if (t > 0) {
            if (tid == 0) {
                const int* p = &g_ctr2[(t - 1) * L2_BTILES + bi];
                while (ld_acquire(p) < L2_UTILES) __nanosleep(32);
            }
            __syncthreads();
            for (int i = tid; i < L2_BT * U2N; i += 256) {
                int b = i & 15, u = i >> 4;
                sh_a[b * L2_P + U1N + u] = g_h2[t - 1][u][b0 + b];
            }
            kmax = L2_K;
        }
        __syncthreads();

        const int khalf = kmax >> 1;
        const int kbeg = kh * khalf, kend = kbeg + khalf;
        unsigned long long acc01 = bias01, acc23 = bias23;
        const float* arow = sh_a + bl * L2_P;
        const ulonglong2* wb = reinterpret_cast<const ulonglong2*>(sh_w) + ul;
#pragma unroll 4
        for (int k = kbeg; k < kend; k += 4) {
            float4 av = *reinterpret_cast<const float4*>(arow + k);
            unsigned long long a0 = pack2(av.x), a1 = pack2(av.y);
            unsigned long long a2 = pack2(av.z), a3 = pack2(av.w);
            ulonglong2 w0 = wb[(k + 0) * 8];
            ulonglong2 w1 = wb[(k + 1) * 8];
            ulonglong2 w2 = wb[(k + 2) * 8];
            ulonglong2 w3 = wb[(k + 3) * 8];
            acc01 = ffma2(a0, w0.x, acc01);  acc23 = ffma2(a0, w0.y, acc23);
            acc01 = ffma2(a1, w1.x, acc01);  acc23 = ffma2(a1, w1.y, acc23);
            acc01 = ffma2(a2, w2.x, acc01);  acc23 = ffma2(a2, w2.y, acc23);
            acc01 = ffma2(a3, w3.x, acc01);  acc23 = ffma2(a3, w3.y, acc23);
        }

        if (kh == 1) {
            sh_red[(tid - 128) * 2 + 0] = acc01;
            sh_red[(tid - 128) * 2 + 1] = acc23;
        }
        __syncthreads();
        if (kh == 0) {
            acc01 = fadd2(acc01, sh_red[tid * 2 + 0]);
            acc23 = fadd2(acc23, sh_red[tid * 2 + 1]);
            float zi, zf, zg, zo;
            unpack2(acc01, zi, zf);
            unpack2(acc23, zg, zo);
            float ig = sigmoidf_(zi), fg = sigmoidf_(zf);
            float gg = fmaxf(zg, 0.0f), og = sigmoidf_(zo);
            c = fg * c + ig * gg;
            float h = og * fmaxf(c, 0.0f);
            if (t == T_STEPS - 1) out[(b0 + bl) * U2N + u0 + ul] = h;
            else                  g_h2[t][u0 + ul][b0 + bl] = h;
        }
        __syncthreads();
        if (tid == 0) {
            __threadfence();
            atomicAdd(&g_ctr2[t * L2_BTILES + bi], 1);
        }
    }
}

// ---------------------------------------------------------------------------
// Launch: reset counters, then the two persistent recurrence kernels.
// 116 KB dynamic smem per CTA forces 1 CTA/SM -> all 128 CTAs co-resident
// (grid <= 148 SMs), so the flag-based step sync cannot deadlock.
// ---------------------------------------------------------------------------
extern "C" void kernel_launch(void* const* d_in, const int* in_sizes, int n_in,
                              void* d_out, int out_size) {
    const float* x  = (const float*)d_in[0];
    const float* W1 = (const float*)d_in[1];
    const float* U1 = (const float*)d_in[2];
    const float* b1 = (const float*)d_in[3];
    const float* W2 = (const float*)d_in[4];
    const float* U2 = (const float*)d_in[5];
    const float* b2 = (const float*)d_in[6];
    float* out = (float*)d_out;

    const int smem_bytes = 116 * 1024;
    cudaFuncSetAttribute(lstm_layer1, cudaFuncAttributeMaxDynamicSharedMemorySize,
                         smem_bytes);
    cudaFuncSetAttribute(lstm_layer2, cudaFuncAttributeMaxDynamicSharedMemorySize,
                         smem_bytes);

    reset_kernel<<<4, 1024>>>();
    lstm_layer1<<<dim3(L1_UTILES, L1_BTILES), 256, smem_bytes>>>(x, W1, U1, b1);
    lstm_layer2<<<dim3(L2_UTILES, L2_BTILES), 256, smem_bytes>>>(W2, U2, b2, out);
}